// round 1
// baseline (speedup 1.0000x reference)
#include <cuda_runtime.h>

#define N_VN    24576
#define D_V     4
#define D_C     8
#define E_EDGES (N_VN * D_V)     // 98304
#define M_CN    (E_EDGES / D_C)  // 12288
#define BSZ     64
#define CLIPV   20.0f
#define EPSV    1e-12f

// ---------------- scratch (device globals: allocation-free) ----------------
__device__ float g_llrT[N_VN * BSZ];      // llr transposed [vn][b]
__device__ float g_belief[N_VN * BSZ];    // belief / final dec [vn][b]
__device__ float g_c2v[E_EDGES * BSZ];    // c2v messages [edge][b]
__device__ int   g_vn_edges[N_VN * D_V];  // inverse map vn -> 4 edges (sorted)
__device__ int   g_vn_cnt[N_VN];

// ---------------- setup kernels ----------------

// llr_in [64][N_VN] -> g_llrT [N_VN][64], tiled through smem
__global__ void k_transpose_in(const float* __restrict__ in) {
    __shared__ float tile[BSZ * 33];
    int n0 = blockIdx.x * 32;
    int t = threadIdx.x;
#pragma unroll
    for (int k = 0; k < 8; k++) {       // 32n x 64b = 2048 elems
        int idx = t + k * 256;
        int nn = idx & 31, b = idx >> 5;
        tile[b * 33 + nn] = in[b * N_VN + n0 + nn];
    }
    __syncthreads();
#pragma unroll
    for (int k = 0; k < 8; k++) {
        int idx = t + k * 256;
        int b = idx & 63, nn = idx >> 6;
        g_llrT[(n0 + nn) * BSZ + b] = tile[b * 33 + nn];
    }
}

// g_belief [N_VN][64] -> out [64][N_VN]
__global__ void k_transpose_out(float* __restrict__ out) {
    __shared__ float tile[BSZ * 33];
    int n0 = blockIdx.x * 32;
    int t = threadIdx.x;
#pragma unroll
    for (int k = 0; k < 8; k++) {
        int idx = t + k * 256;
        int b = idx & 63, nn = idx >> 6;
        tile[b * 33 + nn] = g_belief[(n0 + nn) * BSZ + b];
    }
    __syncthreads();
#pragma unroll
    for (int k = 0; k < 8; k++) {
        int idx = t + k * 256;
        int nn = idx & 31, b = idx >> 5;
        out[b * N_VN + n0 + nn] = tile[b * 33 + nn];
    }
}

__global__ void k_zero_cnt() {
    int i = blockIdx.x * blockDim.x + threadIdx.x;
    if (i < N_VN) g_vn_cnt[i] = 0;
}

__global__ void k_zero_c2v() {
    int i = blockIdx.x * blockDim.x + threadIdx.x;
    if (i < E_EDGES * BSZ / 4)
        reinterpret_cast<float4*>(g_c2v)[i] = make_float4(0.f, 0.f, 0.f, 0.f);
}

__global__ void k_build_inverse(const int* __restrict__ e2v) {
    int e = blockIdx.x * blockDim.x + threadIdx.x;
    if (e < E_EDGES) {
        int n = e2v[e];
        int pos = atomicAdd(&g_vn_cnt[n], 1);
        g_vn_edges[n * D_V + pos] = e;
    }
}

// sort each VN's 4 edges ascending -> deterministic summation order
__global__ void k_sort4() {
    int n = blockIdx.x * blockDim.x + threadIdx.x;
    if (n >= N_VN) return;
    int* p = &g_vn_edges[n * 4];
    int a = p[0], b = p[1], c = p[2], d = p[3], x;
    if (a > b) { x = a; a = b; b = x; }
    if (c > d) { x = c; c = d; d = x; }
    if (a > c) { x = a; a = c; c = x; }
    if (b > d) { x = b; b = d; d = x; }
    if (b > c) { x = b; b = c; c = x; }
    p[0] = a; p[1] = b; p[2] = c; p[3] = d;
}

// ---------------- per-iteration kernels ----------------

// belief[vn][b] = llr*ch_w[it] + sum of the vn's 4 c2v (current)
__global__ void k_vn(const float* __restrict__ ch_w, int it) {
    int idx = blockIdx.x * blockDim.x + threadIdx.x;
    if (idx >= N_VN * BSZ) return;
    int n = idx >> 6, b = idx & 63;
    const int4 e = *reinterpret_cast<const int4*>(&g_vn_edges[n * 4]);
    float c0 = g_c2v[e.x * BSZ + b];
    float c1 = g_c2v[e.y * BSZ + b];
    float c2 = g_c2v[e.z * BSZ + b];
    float c3 = g_c2v[e.w * BSZ + b];
    float s = __fadd_rn(__fadd_rn(__fadd_rn(c0, c1), c2), c3);
    float w = __fmul_rn(g_llrT[idx], __ldg(&ch_w[it]));
    g_belief[idx] = __fadd_rn(w, s);
}

// check-node update: one thread = one (cn, b)
__global__ void k_cn(const float* __restrict__ cn_w,
                     const int* __restrict__ e2v, int it) {
    int idx = blockIdx.x * blockDim.x + threadIdx.x;
    if (idx >= M_CN * BSZ) return;
    int cn = idx >> 6, b = idx & 63;
    int ebase = cn * D_C;

    float t[D_C];
#pragma unroll
    for (int j = 0; j < D_C; j++) {
        int vn = __ldg(&e2v[ebase + j]);
        float bel = g_belief[vn * BSZ + b];
        float c   = g_c2v[(ebase + j) * BSZ + b];
        float v = __fsub_rn(bel, c);
        v = fminf(fmaxf(v, -CLIPV), CLIPV);
        float th = tanhf(__fmul_rn(0.5f, v));
        t[j] = (th == 0.0f) ? EPSV : th;
    }

    float cw = __ldg(&cn_w[it]);
#pragma unroll
    for (int j = 0; j < D_C; j++) {
        // exact left-to-right product of the 7 extrinsic tanh values
        float p = 0.0f;
        bool first = true;
#pragma unroll
        for (int i = 0; i < D_C; i++) {
            if (i == j) continue;
            if (first) { p = t[i]; first = false; }
            else p = __fmul_rn(p, t[i]);
        }
        float o   = fminf(fmaxf(p, -0.999999f), 0.999999f);
        float num = __fadd_rn(1.0f, o);
        float den = __fadd_rn(__fsub_rn(1.0f, o), EPSV);
        float lg  = logf(num / den);                // IEEE div + accurate log
        float u   = fminf(fmaxf(lg, -CLIPV), CLIPV);
        float c2  = fminf(fmaxf(__fmul_rn(u, cw), -CLIPV), CLIPV);
        g_c2v[(ebase + j) * BSZ + b] = c2;
    }
}

// dec[vn][b] = llr + sum of 4 c2v (no channel weight)
__global__ void k_final() {
    int idx = blockIdx.x * blockDim.x + threadIdx.x;
    if (idx >= N_VN * BSZ) return;
    int n = idx >> 6, b = idx & 63;
    const int4 e = *reinterpret_cast<const int4*>(&g_vn_edges[n * 4]);
    float c0 = g_c2v[e.x * BSZ + b];
    float c1 = g_c2v[e.y * BSZ + b];
    float c2 = g_c2v[e.z * BSZ + b];
    float c3 = g_c2v[e.w * BSZ + b];
    float s = __fadd_rn(__fadd_rn(__fadd_rn(c0, c1), c2), c3);
    g_belief[idx] = __fadd_rn(g_llrT[idx], s);
}

// ---------------- launch ----------------
extern "C" void kernel_launch(void* const* d_in, const int* in_sizes, int n_in,
                              void* d_out, int out_size) {
    const float* llr  = (const float*)d_in[0];
    const float* cn_w = (const float*)d_in[1];
    const float* ch_w = (const float*)d_in[2];
    const int*   e2v  = (const int*)d_in[3];
    int iters = in_sizes[1];   // cn_weight length

    k_transpose_in<<<N_VN / 32, 256>>>(llr);
    k_zero_cnt<<<(N_VN + 255) / 256, 256>>>();
    k_build_inverse<<<(E_EDGES + 255) / 256, 256>>>(e2v);
    k_sort4<<<(N_VN + 255) / 256, 256>>>();
    k_zero_c2v<<<(E_EDGES * BSZ / 4 + 255) / 256, 256>>>();

    for (int it = 0; it < iters; it++) {
        k_vn<<<(N_VN * BSZ) / 256, 256>>>(ch_w, it);
        k_cn<<<(M_CN * BSZ) / 256, 256>>>(cn_w, e2v, it);
    }

    k_final<<<(N_VN * BSZ) / 256, 256>>>();
    k_transpose_out<<<N_VN / 32, 256>>>((float*)d_out);
}

// round 2
// speedup vs baseline: 1.1619x; 1.1619x over previous
#include <cuda_runtime.h>

#define N_VN    24576
#define D_V     4
#define D_C     8
#define E_EDGES (N_VN * D_V)     // 98304
#define M_CN    (E_EDGES / D_C)  // 12288
#define BSZ     64
#define CLIPV   20.0f
#define EPSV    1e-12f

// ---------------- scratch (device globals: allocation-free) ----------------
__device__ float g_llrT[N_VN * BSZ];      // llr transposed [vn][b]
__device__ float g_belief[N_VN * BSZ];    // belief [vn][b]
__device__ float g_c2v[E_EDGES * BSZ];    // c2v messages [edge][b]
__device__ int   g_vn_edges[N_VN * D_V];  // inverse map vn -> 4 edges (sorted)
__device__ int   g_vn_cnt[N_VN];

__device__ __forceinline__ float clipf(float v, float lo, float hi) {
    return fminf(fmaxf(v, lo), hi);
}

// tanh(0.5*v) = (e^v - 1)/(e^v + 1), v in [-20,20].
// Computes (1 - t) with good RELATIVE accuracy, so the downstream atanh
// amplification near the saturation clip cancels instead of exploding.
__device__ __forceinline__ float tanh_half(float v) {
    float e = __expf(v);
    float r = __frcp_rn(e + 1.0f);
    float t = (e - 1.0f) * r;
    return (t == 0.0f) ? EPSV : t;
}

__device__ __forceinline__ float cn_out(float p, float cw) {
    float o   = clipf(p, -0.999999f, 0.999999f);
    float num = 1.0f + o;
    float den = (1.0f - o) + EPSV;
    float lg  = __logf(num * __frcp_rn(den));
    float u   = clipf(lg, -CLIPV, CLIPV);
    return clipf(u * cw, -CLIPV, CLIPV);
}

// ---------------- setup: transpose llr + zero cnt + zero c2v ----------------
__global__ void k_setup(const float* __restrict__ in) {
    __shared__ float tile[BSZ * 33];
    int n0 = blockIdx.x * 32;
    int t = threadIdx.x;
#pragma unroll
    for (int k = 0; k < 8; k++) {       // load 32n x 64b tile (b-major source)
        int idx = t + k * 256;
        int nn = idx & 31, b = idx >> 5;
        tile[b * 33 + nn] = in[b * N_VN + n0 + nn];
    }
    if (t < 32) g_vn_cnt[n0 + t] = 0;
    {   // zero this block's slice of c2v: 2048 float4 per block x 768 blocks
        float4* c4 = reinterpret_cast<float4*>(g_c2v);
        int base = blockIdx.x * 2048;
#pragma unroll
        for (int k = 0; k < 8; k++)
            c4[base + t + k * 256] = make_float4(0.f, 0.f, 0.f, 0.f);
    }
    __syncthreads();
#pragma unroll
    for (int k = 0; k < 8; k++) {
        int idx = t + k * 256;
        int b = idx & 63, nn = idx >> 6;
        g_llrT[(n0 + nn) * BSZ + b] = tile[b * 33 + nn];
    }
}

__global__ void k_build_inverse(const int* __restrict__ e2v) {
    int e = blockIdx.x * blockDim.x + threadIdx.x;
    if (e < E_EDGES) {
        int n = e2v[e];
        int pos = atomicAdd(&g_vn_cnt[n], 1);
        g_vn_edges[n * D_V + pos] = e;
    }
}

// sort each VN's 4 edges ascending -> deterministic summation order
__global__ void k_sort4() {
    int n = blockIdx.x * blockDim.x + threadIdx.x;
    if (n >= N_VN) return;
    int* p = &g_vn_edges[n * 4];
    int a = p[0], b = p[1], c = p[2], d = p[3], x;
    if (a > b) { x = a; a = b; b = x; }
    if (c > d) { x = c; c = d; d = x; }
    if (a > c) { x = a; a = c; c = x; }
    if (b > d) { x = b; b = d; d = x; }
    if (b > c) { x = b; b = c; c = x; }
    p[0] = a; p[1] = b; p[2] = c; p[3] = d;
}

// ---------------- per-iteration kernels ----------------

// belief[vn][b] = llr*ch_w[it] + sum of the vn's 4 c2v; float4 over batch
__global__ void k_vn(const float* __restrict__ ch_w, int it) {
    int idx = blockIdx.x * blockDim.x + threadIdx.x;   // N_VN * 16
    int n = idx >> 4, q = idx & 15;
    const int4 e = *reinterpret_cast<const int4*>(&g_vn_edges[n * 4]);
    const float4* c4 = reinterpret_cast<const float4*>(g_c2v);
    float4 a = c4[e.x * 16 + q];
    float4 b = c4[e.y * 16 + q];
    float4 c = c4[e.z * 16 + q];
    float4 d = c4[e.w * 16 + q];
    float4 L = reinterpret_cast<const float4*>(g_llrT)[n * 16 + q];
    float w = __ldg(&ch_w[it]);
    float4 o;
    o.x = L.x * w + (((a.x + b.x) + c.x) + d.x);
    o.y = L.y * w + (((a.y + b.y) + c.y) + d.y);
    o.z = L.z * w + (((a.z + b.z) + c.z) + d.z);
    o.w = L.w * w + (((a.w + b.w) + c.w) + d.w);
    reinterpret_cast<float4*>(g_belief)[n * 16 + q] = o;
}

// check-node update: one thread = one (cn, pair of batch lanes)
__global__ void k_cn(const float* __restrict__ cn_w,
                     const int* __restrict__ e2v, int it) {
    int idx = blockIdx.x * blockDim.x + threadIdx.x;   // M_CN * 32
    int cn = idx >> 5, q = idx & 31;
    int ebase = cn * D_C;
    const float2* c2   = reinterpret_cast<const float2*>(g_c2v);
    const float2* bel2 = reinterpret_cast<const float2*>(g_belief);

    float2 t[D_C];
#pragma unroll
    for (int j = 0; j < D_C; j++) {
        int vn = __ldg(&e2v[ebase + j]);
        float2 B = bel2[vn * 32 + q];
        float2 C = c2[(ebase + j) * 32 + q];
        float vx = clipf(B.x - C.x, -CLIPV, CLIPV);
        float vy = clipf(B.y - C.y, -CLIPV, CLIPV);
        t[j].x = tanh_half(vx);
        t[j].y = tanh_half(vy);
    }

    // suffix products: suf[j] = prod_{i>j} t[i]
    float2 suf[D_C];
    suf[D_C - 1] = make_float2(1.0f, 1.0f);
#pragma unroll
    for (int j = D_C - 2; j >= 0; j--) {
        suf[j].x = t[j + 1].x * suf[j + 1].x;
        suf[j].y = t[j + 1].y * suf[j + 1].y;
    }

    float cw = __ldg(&cn_w[it]);
    float2* c2w = reinterpret_cast<float2*>(g_c2v);
    float px = 1.0f, py = 1.0f;                 // running prefix
#pragma unroll
    for (int j = 0; j < D_C; j++) {
        float ex = px * suf[j].x;
        float ey = py * suf[j].y;
        float2 o;
        o.x = cn_out(ex, cw);
        o.y = cn_out(ey, cw);
        c2w[(ebase + j) * 32 + q] = o;
        px *= t[j].x;
        py *= t[j].y;
    }
}

// ---------------- final: dec = llr_in + sum c2v, written back transposed ----
__global__ void k_out(const float* __restrict__ in, float* __restrict__ out) {
    __shared__ float tile[BSZ * 33];
    int n0 = blockIdx.x * 32;
    int t = threadIdx.x;
#pragma unroll
    for (int k = 0; k < 8; k++) {       // b-fast mapping: coalesced c2v reads
        int idx = t + k * 256;
        int b = idx & 63, nn = idx >> 6;
        int n = n0 + nn;
        const int4 e = *reinterpret_cast<const int4*>(&g_vn_edges[n * 4]);
        float s = ((g_c2v[e.x * BSZ + b] + g_c2v[e.y * BSZ + b])
                   + g_c2v[e.z * BSZ + b]) + g_c2v[e.w * BSZ + b];
        tile[b * 33 + nn] = s;
    }
    __syncthreads();
#pragma unroll
    for (int k = 0; k < 8; k++) {       // n-fast mapping: coalesced out writes
        int idx = t + k * 256;
        int nn = idx & 31, b = idx >> 5;
        out[b * N_VN + n0 + nn] = in[b * N_VN + n0 + nn] + tile[b * 33 + nn];
    }
}

// ---------------- launch ----------------
extern "C" void kernel_launch(void* const* d_in, const int* in_sizes, int n_in,
                              void* d_out, int out_size) {
    const float* llr  = (const float*)d_in[0];
    const float* cn_w = (const float*)d_in[1];
    const float* ch_w = (const float*)d_in[2];
    const int*   e2v  = (const int*)d_in[3];
    int iters = in_sizes[1];   // cn_weight length

    k_setup<<<N_VN / 32, 256>>>(llr);
    k_build_inverse<<<(E_EDGES + 255) / 256, 256>>>(e2v);
    k_sort4<<<(N_VN + 255) / 256, 256>>>();

    for (int it = 0; it < iters; it++) {
        k_vn<<<(N_VN * 16) / 256, 256>>>(ch_w, it);
        k_cn<<<(M_CN * 32) / 256, 256>>>(cn_w, e2v, it);
    }

    k_out<<<N_VN / 32, 256>>>(llr, (float*)d_out);
}

// round 3
// speedup vs baseline: 1.1839x; 1.0189x over previous
#include <cuda_runtime.h>
#include <cuda_fp16.h>

#define N_VN    24576
#define D_V     4
#define D_C     8
#define E_EDGES (N_VN * D_V)     // 98304
#define M_CN    (E_EDGES / D_C)  // 12288
#define BSZ     64
#define CLIPV   20.0f
#define EPSV    1e-12f

// ---------------- scratch (device globals: allocation-free) ----------------
__device__ float  g_llrT[N_VN * BSZ];      // llr transposed [vn][b]
__device__ float  g_belief[N_VN * BSZ];    // belief [vn][b] (fp32)
__device__ __half g_c2v[E_EDGES * BSZ];    // c2v messages [edge][b] (fp16)
__device__ int    g_vn_edges[N_VN * D_V];  // inverse map vn -> 4 edges (sorted)
__device__ int    g_vn_cnt[N_VN];

__device__ __forceinline__ float clipf(float v, float lo, float hi) {
    return fminf(fmaxf(v, lo), hi);
}

// tanh(0.5*v) = (e^v - 1)/(e^v + 1): keeps (1 - t) relatively accurate so the
// downstream atanh amplification near saturation cancels.
__device__ __forceinline__ float tanh_half(float v) {
    float e = __expf(v);
    float r = __frcp_rn(e + 1.0f);
    float t = (e - 1.0f) * r;
    return (t == 0.0f) ? EPSV : t;
}

__device__ __forceinline__ float cn_out(float p, float cw) {
    float o   = clipf(p, -0.999999f, 0.999999f);
    float num = 1.0f + o;
    float den = (1.0f - o) + EPSV;
    float lg  = __logf(num * __frcp_rn(den));
    float u   = clipf(lg, -CLIPV, CLIPV);
    return clipf(u * cw, -CLIPV, CLIPV);
}

// ---------------- setup: transpose llr + zero cnt + zero c2v ----------------
__global__ void k_setup(const float* __restrict__ in) {
    __shared__ float tile[BSZ * 33];
    int n0 = blockIdx.x * 32;
    int t = threadIdx.x;
#pragma unroll
    for (int k = 0; k < 8; k++) {       // load 32n x 64b tile (b-major source)
        int idx = t + k * 256;
        int nn = idx & 31, b = idx >> 5;
        tile[b * 33 + nn] = in[b * N_VN + n0 + nn];
    }
    if (t < 32) g_vn_cnt[n0 + t] = 0;
    {   // zero this block's slice of c2v (fp16): 1024 uint4 per block
        uint4* c4 = reinterpret_cast<uint4*>(g_c2v);
        int base = blockIdx.x * 1024;
#pragma unroll
        for (int k = 0; k < 4; k++)
            c4[base + t + k * 256] = make_uint4(0u, 0u, 0u, 0u);
    }
    __syncthreads();
#pragma unroll
    for (int k = 0; k < 8; k++) {
        int idx = t + k * 256;
        int b = idx & 63, nn = idx >> 6;
        g_llrT[(n0 + nn) * BSZ + b] = tile[b * 33 + nn];
    }
}

__global__ void k_build_inverse(const int* __restrict__ e2v) {
    int e = blockIdx.x * blockDim.x + threadIdx.x;
    if (e < E_EDGES) {
        int n = e2v[e];
        int pos = atomicAdd(&g_vn_cnt[n], 1);
        g_vn_edges[n * D_V + pos] = e;
    }
}

// sort each VN's 4 edges ascending -> deterministic summation order
__global__ void k_sort4() {
    int n = blockIdx.x * blockDim.x + threadIdx.x;
    if (n >= N_VN) return;
    int* p = &g_vn_edges[n * 4];
    int a = p[0], b = p[1], c = p[2], d = p[3], x;
    if (a > b) { x = a; a = b; b = x; }
    if (c > d) { x = c; c = d; d = x; }
    if (a > c) { x = a; a = c; c = x; }
    if (b > d) { x = b; b = d; d = x; }
    if (b > c) { x = b; b = c; c = x; }
    p[0] = a; p[1] = b; p[2] = c; p[3] = d;
}

// ---------------- per-iteration kernels ----------------

// belief[vn][b] = llr*ch_w + sum of the vn's 4 c2v; 4 batch lanes per thread
__global__ void k_vn(const float* __restrict__ ch_w, int it) {
    int idx = blockIdx.x * blockDim.x + threadIdx.x;   // N_VN * 16
    int n = idx >> 4, q = idx & 15;
    const int4 e = *reinterpret_cast<const int4*>(&g_vn_edges[n * 4]);
    const uint2* c4 = reinterpret_cast<const uint2*>(g_c2v);  // 4 halves
    uint2 ua = c4[e.x * 16 + q];
    uint2 ub = c4[e.y * 16 + q];
    uint2 uc = c4[e.z * 16 + q];
    uint2 ud = c4[e.w * 16 + q];
    float2 a0 = __half22float2(*reinterpret_cast<__half2*>(&ua.x));
    float2 a1 = __half22float2(*reinterpret_cast<__half2*>(&ua.y));
    float2 b0 = __half22float2(*reinterpret_cast<__half2*>(&ub.x));
    float2 b1 = __half22float2(*reinterpret_cast<__half2*>(&ub.y));
    float2 c0 = __half22float2(*reinterpret_cast<__half2*>(&uc.x));
    float2 c1 = __half22float2(*reinterpret_cast<__half2*>(&uc.y));
    float2 d0 = __half22float2(*reinterpret_cast<__half2*>(&ud.x));
    float2 d1 = __half22float2(*reinterpret_cast<__half2*>(&ud.y));
    float4 L = reinterpret_cast<const float4*>(g_llrT)[idx];
    float w = __ldg(&ch_w[it]);
    float4 o;
    o.x = L.x * w + (((a0.x + b0.x) + c0.x) + d0.x);
    o.y = L.y * w + (((a0.y + b0.y) + c0.y) + d0.y);
    o.z = L.z * w + (((a1.x + b1.x) + c1.x) + d1.x);
    o.w = L.w * w + (((a1.y + b1.y) + c1.y) + d1.y);
    reinterpret_cast<float4*>(g_belief)[idx] = o;
}

// check-node update: one thread = one (cn, pair of batch lanes)
__global__ void k_cn(const float* __restrict__ cn_w,
                     const int* __restrict__ e2v, int it) {
    int idx = blockIdx.x * blockDim.x + threadIdx.x;   // M_CN * 32
    int cn = idx >> 5, q = idx & 31;
    int ebase = cn * D_C;
    const __half2* c2   = reinterpret_cast<const __half2*>(g_c2v);
    const float2*  bel2 = reinterpret_cast<const float2*>(g_belief);

    float2 t[D_C];
#pragma unroll
    for (int j = 0; j < D_C; j++) {
        int vn = __ldg(&e2v[ebase + j]);
        float2 B = bel2[vn * 32 + q];
        float2 C = __half22float2(c2[(ebase + j) * 32 + q]);
        float vx = clipf(B.x - C.x, -CLIPV, CLIPV);
        float vy = clipf(B.y - C.y, -CLIPV, CLIPV);
        t[j].x = tanh_half(vx);
        t[j].y = tanh_half(vy);
    }

    // suffix products: suf[j] = prod_{i>j} t[i]
    float2 suf[D_C];
    suf[D_C - 1] = make_float2(1.0f, 1.0f);
#pragma unroll
    for (int j = D_C - 2; j >= 0; j--) {
        suf[j].x = t[j + 1].x * suf[j + 1].x;
        suf[j].y = t[j + 1].y * suf[j + 1].y;
    }

    float cw = __ldg(&cn_w[it]);
    __half2* c2w = reinterpret_cast<__half2*>(g_c2v);
    float px = 1.0f, py = 1.0f;                 // running prefix
#pragma unroll
    for (int j = 0; j < D_C; j++) {
        float ox = cn_out(px * suf[j].x, cw);
        float oy = cn_out(py * suf[j].y, cw);
        c2w[(ebase + j) * 32 + q] = __floats2half2_rn(ox, oy);
        px *= t[j].x;
        py *= t[j].y;
    }
}

// ---------------- final: dec = llr_in + sum c2v, written back transposed ----
__global__ void k_out(const float* __restrict__ in, float* __restrict__ out) {
    __shared__ float tile[BSZ * 33];
    int n0 = blockIdx.x * 32;
    int t = threadIdx.x;
#pragma unroll
    for (int k = 0; k < 8; k++) {       // b-fast mapping: coalesced c2v reads
        int idx = t + k * 256;
        int b = idx & 63, nn = idx >> 6;
        int n = n0 + nn;
        const int4 e = *reinterpret_cast<const int4*>(&g_vn_edges[n * 4]);
        float s = ((__half2float(g_c2v[e.x * BSZ + b]) +
                    __half2float(g_c2v[e.y * BSZ + b])) +
                    __half2float(g_c2v[e.z * BSZ + b])) +
                    __half2float(g_c2v[e.w * BSZ + b]);
        tile[b * 33 + nn] = s;
    }
    __syncthreads();
#pragma unroll
    for (int k = 0; k < 8; k++) {       // n-fast mapping: coalesced out writes
        int idx = t + k * 256;
        int nn = idx & 31, b = idx >> 5;
        out[b * N_VN + n0 + nn] = in[b * N_VN + n0 + nn] + tile[b * 33 + nn];
    }
}

// ---------------- launch ----------------
extern "C" void kernel_launch(void* const* d_in, const int* in_sizes, int n_in,
                              void* d_out, int out_size) {
    const float* llr  = (const float*)d_in[0];
    const float* cn_w = (const float*)d_in[1];
    const float* ch_w = (const float*)d_in[2];
    const int*   e2v  = (const int*)d_in[3];
    int iters = in_sizes[1];   // cn_weight length

    k_setup<<<N_VN / 32, 256>>>(llr);
    k_build_inverse<<<(E_EDGES + 255) / 256, 256>>>(e2v);
    k_sort4<<<(N_VN + 255) / 256, 256>>>();

    for (int it = 0; it < iters; it++) {
        k_vn<<<(N_VN * 16) / 256, 256>>>(ch_w, it);
        k_cn<<<(M_CN * 32) / 256, 256>>>(cn_w, e2v, it);
    }

    k_out<<<N_VN / 32, 256>>>(llr, (float*)d_out);
}

// round 5
// speedup vs baseline: 1.4835x; 1.2531x over previous
#include <cuda_runtime.h>
#include <cuda_fp16.h>

#define N_VN    24576
#define D_V     4
#define D_C     8
#define E_EDGES (N_VN * D_V)     // 98304
#define M_CN    (E_EDGES / D_C)  // 12288
#define BSZ     64
#define CLIPV   20.0f
#define EPSV    1e-12f

#define PLANEH2 (N_VN * 32)      // __half2 elements per plane (32 = BSZ/2)
#define BUFH2   (4 * PLANEH2)    // __half2 elements per buffer (4 slots)

// ---------------- scratch (device globals: allocation-free) ----------------
__device__ float   g_llrT[N_VN * BSZ];       // llr transposed [vn][b]
__device__ __half2 g_c2v[2 * BUFH2];         // double-buffered planes [buf][slot][vn][b/2]
__device__ int     g_vn_edges[N_VN * D_V];   // vn -> its 4 edges (sorted)
__device__ int     g_e2vs[E_EDGES];          // edge -> vn*4 + slot
__device__ int     g_vn_cnt[N_VN];

__device__ __forceinline__ float clipf(float v, float lo, float hi) {
    return fminf(fmaxf(v, lo), hi);
}

// tanh(0.5*v) = (e^v - 1)/(e^v + 1): keeps (1 - t) relatively accurate so the
// downstream atanh amplification near saturation cancels.
__device__ __forceinline__ float tanh_half(float v) {
    float e = __expf(v);
    float t = __fdividef(e - 1.0f, e + 1.0f);
    return (t == 0.0f) ? EPSV : t;
}

__device__ __forceinline__ float cn_out(float p, float cw) {
    float o  = clipf(p, -0.999999f, 0.999999f);
    float lg = __logf(__fdividef(1.0f + o, (1.0f - o) + EPSV));
    float u  = clipf(lg, -CLIPV, CLIPV);
    return clipf(u * cw, -CLIPV, CLIPV);
}

// ------------- setup: transpose llr + zero cnt + zero c2v buf0 -------------
__global__ void k_setup(const float* __restrict__ in) {
    __shared__ float tile[BSZ * 33];
    int n0 = blockIdx.x * 32;
    int t = threadIdx.x;
#pragma unroll
    for (int k = 0; k < 8; k++) {       // load 32n x 64b tile (b-major source)
        int idx = t + k * 256;
        int nn = idx & 31, b = idx >> 5;
        tile[b * 33 + nn] = in[b * N_VN + n0 + nn];
    }
    if (t < 32) g_vn_cnt[n0 + t] = 0;
    {   // zero buffer 0 of c2v: 1024 uint4 per block x 768 blocks
        uint4* c4 = reinterpret_cast<uint4*>(g_c2v);
        int base = blockIdx.x * 1024;
#pragma unroll
        for (int k = 0; k < 4; k++)
            c4[base + t + k * 256] = make_uint4(0u, 0u, 0u, 0u);
    }
    __syncthreads();
#pragma unroll
    for (int k = 0; k < 8; k++) {
        int idx = t + k * 256;
        int b = idx & 63, nn = idx >> 6;
        g_llrT[(n0 + nn) * BSZ + b] = tile[b * 33 + nn];
    }
}

__global__ void k_build_inverse(const int* __restrict__ e2v) {
    int e = blockIdx.x * blockDim.x + threadIdx.x;
    if (e < E_EDGES) {
        int n = e2v[e];
        int pos = atomicAdd(&g_vn_cnt[n], 1);
        g_vn_edges[n * D_V + pos] = e;
    }
}

// sort each VN's 4 edges ascending (deterministic slots), emit edge->(vn,slot)
__global__ void k_sort4() {
    int n = blockIdx.x * blockDim.x + threadIdx.x;
    if (n >= N_VN) return;
    int* p = &g_vn_edges[n * 4];
    int a = p[0], b = p[1], c = p[2], d = p[3], x;
    if (a > b) { x = a; a = b; b = x; }
    if (c > d) { x = c; c = d; d = x; }
    if (a > c) { x = a; a = c; c = x; }
    if (b > d) { x = b; b = d; d = x; }
    if (b > c) { x = b; b = c; c = x; }
    p[0] = a; p[1] = b; p[2] = c; p[3] = d;
    g_e2vs[a] = n * 4 + 0;
    g_e2vs[b] = n * 4 + 1;
    g_e2vs[c] = n * 4 + 2;
    g_e2vs[d] = n * 4 + 3;
}

// ------------- fused per-iteration kernel: belief-on-the-fly CN ------------
// One warp = one CN (32 threads x 2 batch lanes = 64). Reads c2v from buffer
// rb, writes updated c2v to buffer rb^1 (double buffer: no RAW race).
__global__ void __launch_bounds__(256) k_cn(const float* __restrict__ cn_w,
                                            const float* __restrict__ ch_w,
                                            int it, int rb) {
    int idx = blockIdx.x * blockDim.x + threadIdx.x;   // M_CN * 32
    int cn = idx >> 5, q = idx & 31;
    int ebase = cn * D_C;
    float cw  = __ldg(&cn_w[it]);
    float chw = __ldg(&ch_w[it]);
    const __half2* rp = g_c2v + rb * BUFH2;
    __half2*       wp = g_c2v + (rb ^ 1) * BUFH2;
    const float2* llr2 = reinterpret_cast<const float2*>(g_llrT);

    float2 t[D_C];
    int vsl[D_C];
#pragma unroll
    for (int j = 0; j < D_C; j++) {
        int v = __ldg(&g_e2vs[ebase + j]);      // broadcast (same for warp)
        vsl[j] = v;
        int vn = v >> 2, slot = v & 3;
        int base = vn * 32 + q;
        float2 c0 = __half22float2(rp[base]);
        float2 c1 = __half22float2(rp[PLANEH2 + base]);
        float2 c2 = __half22float2(rp[2 * PLANEH2 + base]);
        float2 c3 = __half22float2(rp[3 * PLANEH2 + base]);
        float2 L  = llr2[base];
        float sx = ((c0.x + c1.x) + c2.x) + c3.x;
        float sy = ((c0.y + c1.y) + c2.y) + c3.y;
        float cjx = (slot == 0) ? c0.x : (slot == 1) ? c1.x : (slot == 2) ? c2.x : c3.x;
        float cjy = (slot == 0) ? c0.y : (slot == 1) ? c1.y : (slot == 2) ? c2.y : c3.y;
        float vx = clipf((fmaf(L.x, chw, sx)) - cjx, -CLIPV, CLIPV);
        float vy = clipf((fmaf(L.y, chw, sy)) - cjy, -CLIPV, CLIPV);
        t[j].x = tanh_half(vx);
        t[j].y = tanh_half(vy);
    }

    // suffix products: suf[j] = prod_{i>j} t[i]
    float2 suf[D_C];
    suf[D_C - 1] = make_float2(1.0f, 1.0f);
#pragma unroll
    for (int j = D_C - 2; j >= 0; j--) {
        suf[j].x = t[j + 1].x * suf[j + 1].x;
        suf[j].y = t[j + 1].y * suf[j + 1].y;
    }

    float px = 1.0f, py = 1.0f;                 // running prefix
#pragma unroll
    for (int j = 0; j < D_C; j++) {
        float ox = cn_out(px * suf[j].x, cw);
        float oy = cn_out(py * suf[j].y, cw);
        int v = vsl[j];
        wp[(v & 3) * PLANEH2 + (v >> 2) * 32 + q] = __floats2half2_rn(ox, oy);
        px *= t[j].x;
        py *= t[j].y;
    }
}

// ---------------- final: dec = llr_in + sum c2v, transposed out ------------
__global__ void k_out(const float* __restrict__ in, float* __restrict__ out,
                      int fb) {
    __shared__ float tile[BSZ * 33];
    const __half* cv = reinterpret_cast<const __half*>(g_c2v + fb * BUFH2);
    int n0 = blockIdx.x * 32;
    int t = threadIdx.x;
#pragma unroll
    for (int k = 0; k < 8; k++) {       // b-fast mapping: coalesced plane reads
        int idx = t + k * 256;
        int b = idx & 63, nn = idx >> 6;
        int n = n0 + nn;
        float s = ((__half2float(cv[0 * N_VN * BSZ + n * BSZ + b]) +
                    __half2float(cv[1 * N_VN * BSZ + n * BSZ + b])) +
                    __half2float(cv[2 * N_VN * BSZ + n * BSZ + b])) +
                    __half2float(cv[3 * N_VN * BSZ + n * BSZ + b]);
        tile[b * 33 + nn] = s;
    }
    __syncthreads();
#pragma unroll
    for (int k = 0; k < 8; k++) {       // n-fast mapping: coalesced out writes
        int idx = t + k * 256;
        int nn = idx & 31, b = idx >> 5;
        out[b * N_VN + n0 + nn] = in[b * N_VN + n0 + nn] + tile[b * 33 + nn];
    }
}

// ---------------- launch ----------------
extern "C" void kernel_launch(void* const* d_in, const int* in_sizes, int n_in,
                              void* d_out, int out_size) {
    const float* llr  = (const float*)d_in[0];
    const float* cn_w = (const float*)d_in[1];
    const float* ch_w = (const float*)d_in[2];
    const int*   e2v  = (const int*)d_in[3];
    int iters = in_sizes[1];   // cn_weight length

    k_setup<<<N_VN / 32, 256>>>(llr);
    k_build_inverse<<<(E_EDGES + 255) / 256, 256>>>(e2v);
    k_sort4<<<(N_VN + 255) / 256, 256>>>();

    for (int it = 0; it < iters; it++)
        k_cn<<<(M_CN * 32) / 256, 256>>>(cn_w, ch_w, it, it & 1);

    k_out<<<N_VN / 32, 256>>>(llr, (float*)d_out, iters & 1);
}

// round 6
// speedup vs baseline: 1.7205x; 1.1598x over previous
#include <cuda_runtime.h>
#include <cuda_fp16.h>

#define N_VN    24576
#define D_V     4
#define D_C     8
#define E_EDGES (N_VN * D_V)     // 98304
#define M_CN    (E_EDGES / D_C)  // 12288
#define BSZ     64
#define CLIPV   20.0f
#define EPSV    1e-12f

#define PLANEU2 (N_VN * 16)      // uint2 (=4 halves) elements per plane
#define BUFU2   (4 * PLANEU2)    // uint2 elements per buffer (4 slots)

// ---------------- scratch (device globals: allocation-free) ----------------
__device__ float g_llrT[N_VN * BSZ];       // llr transposed [vn][b]
__device__ uint2 g_c2v[2 * BUFU2];         // double-buffered planes [buf][slot][vn][b/4]
__device__ int   g_vn_edges[N_VN * D_V];   // vn -> its 4 edges (sorted)
__device__ int2  g_eidx[E_EDGES];          // edge -> {vn*16, slot*PLANEU2+vn*16}
__device__ int   g_vn_cnt[N_VN];

__device__ __forceinline__ float clipf(float v, float lo, float hi) {
    return fminf(fmaxf(v, lo), hi);
}
__device__ __forceinline__ __half2 h2(unsigned u) {
    return *reinterpret_cast<__half2*>(&u);
}

// tanh(0.5*v) = (e^v - 1)/(e^v + 1): keeps (1 - t) relatively accurate so the
// downstream atanh amplification near saturation cancels.
__device__ __forceinline__ float tanh_half(float v) {
    float e = __expf(v);
    return __fdividef(e - 1.0f, e + 1.0f);
}

__device__ __forceinline__ float cn_out(float p, float cw) {
    float o  = clipf(p, -0.999999f, 0.999999f);
    float lg = __logf(__fdividef(1.0f + o, (1.0f - o) + EPSV));
    float u  = clipf(lg, -CLIPV, CLIPV);
    return clipf(u * cw, -CLIPV, CLIPV);
}

// ------------- setup: transpose llr + zero cnt + zero c2v buf0 -------------
__global__ void k_setup(const float* __restrict__ in) {
    __shared__ float tile[BSZ * 33];
    int n0 = blockIdx.x * 32;
    int t = threadIdx.x;
#pragma unroll
    for (int k = 0; k < 8; k++) {       // load 32n x 64b tile (b-major source)
        int idx = t + k * 256;
        int nn = idx & 31, b = idx >> 5;
        tile[b * 33 + nn] = in[b * N_VN + n0 + nn];
    }
    if (t < 32) g_vn_cnt[n0 + t] = 0;
    {   // zero buffer 0 of c2v: 1024 uint4 per block x 768 blocks
        uint4* c4 = reinterpret_cast<uint4*>(g_c2v);
        int base = blockIdx.x * 1024;
#pragma unroll
        for (int k = 0; k < 4; k++)
            c4[base + t + k * 256] = make_uint4(0u, 0u, 0u, 0u);
    }
    __syncthreads();
#pragma unroll
    for (int k = 0; k < 8; k++) {
        int idx = t + k * 256;
        int b = idx & 63, nn = idx >> 6;
        g_llrT[(n0 + nn) * BSZ + b] = tile[b * 33 + nn];
    }
}

__global__ void k_build_inverse(const int* __restrict__ e2v) {
    int e = blockIdx.x * blockDim.x + threadIdx.x;
    if (e < E_EDGES) {
        int n = e2v[e];
        int pos = atomicAdd(&g_vn_cnt[n], 1);
        g_vn_edges[n * D_V + pos] = e;
    }
}

// sort each VN's 4 edges ascending (deterministic slots); emit index table
__global__ void k_sort4() {
    int n = blockIdx.x * blockDim.x + threadIdx.x;
    if (n >= N_VN) return;
    int* p = &g_vn_edges[n * 4];
    int a = p[0], b = p[1], c = p[2], d = p[3], x;
    if (a > b) { x = a; a = b; b = x; }
    if (c > d) { x = c; c = d; d = x; }
    if (a > c) { x = a; a = c; c = x; }
    if (b > d) { x = b; b = d; d = x; }
    if (b > c) { x = b; b = c; c = x; }
    p[0] = a; p[1] = b; p[2] = c; p[3] = d;
    int ro = n * 16;
    g_eidx[a] = make_int2(ro, 0 * PLANEU2 + ro);
    g_eidx[b] = make_int2(ro, 1 * PLANEU2 + ro);
    g_eidx[c] = make_int2(ro, 2 * PLANEU2 + ro);
    g_eidx[d] = make_int2(ro, 3 * PLANEU2 + ro);
}

// ------------- fused per-iteration kernel: belief-on-the-fly CN ------------
// One thread = one CN x 4 batch lanes (16 threads per CN). Reads buffer rb,
// writes buffer rb^1 (double buffer: no RAW race).
__global__ void __launch_bounds__(256, 2) k_cn(const float* __restrict__ cn_w,
                                               const float* __restrict__ ch_w,
                                               int it, int rb) {
    int idx = blockIdx.x * blockDim.x + threadIdx.x;   // M_CN * 16
    int cn = idx >> 4, qq = idx & 15;
    int ebase = cn * D_C;
    float cw  = __ldg(&cn_w[it]);
    float chw = __ldg(&ch_w[it]);
    const uint2* rp = g_c2v + rb * BUFU2;
    uint2*       wp = g_c2v + (rb ^ 1) * BUFU2;
    const float4* llr4 = reinterpret_cast<const float4*>(g_llrT);

    float4 t[D_C], p[D_C];
    int wof[D_C];
#pragma unroll
    for (int j = 0; j < D_C; j++) {
        int2 ix = __ldg(&g_eidx[ebase + j]);   // broadcast within half-warp
        int ro = ix.x + qq;
        wof[j] = ix.y + qq;
        uint2 u0 = rp[ro];
        uint2 u1 = rp[ro + PLANEU2];
        uint2 u2 = rp[ro + 2 * PLANEU2];
        uint2 u3 = rp[ro + 3 * PLANEU2];
        uint2 uo = rp[wof[j]];                 // own c2v (no slot selects)
        // fp16 tree-sum of the 4 slot planes
        __half2 sA = __hadd2(__hadd2(h2(u0.x), h2(u1.x)), __hadd2(h2(u2.x), h2(u3.x)));
        __half2 sB = __hadd2(__hadd2(h2(u0.y), h2(u1.y)), __hadd2(h2(u2.y), h2(u3.y)));
        float2 sa = __half22float2(sA), sb = __half22float2(sB);
        float2 oa = __half22float2(h2(uo.x)), ob = __half22float2(h2(uo.y));
        float4 L = llr4[ro];
        float vx = clipf(fmaf(L.x, chw, sa.x) - oa.x, -CLIPV, CLIPV);
        float vy = clipf(fmaf(L.y, chw, sa.y) - oa.y, -CLIPV, CLIPV);
        float vz = clipf(fmaf(L.z, chw, sb.x) - ob.x, -CLIPV, CLIPV);
        float vw = clipf(fmaf(L.w, chw, sb.y) - ob.y, -CLIPV, CLIPV);
        t[j].x = tanh_half(vx);
        t[j].y = tanh_half(vy);
        t[j].z = tanh_half(vz);
        t[j].w = tanh_half(vw);
        if (j == 0) {
            p[0] = make_float4(1.f, 1.f, 1.f, 1.f);
        } else {
            p[j].x = p[j - 1].x * t[j - 1].x;
            p[j].y = p[j - 1].y * t[j - 1].y;
            p[j].z = p[j - 1].z * t[j - 1].z;
            p[j].w = p[j - 1].w * t[j - 1].w;
        }
    }

    float4 S = make_float4(1.f, 1.f, 1.f, 1.f);
#pragma unroll
    for (int j = D_C - 1; j >= 0; j--) {
        float ex = p[j].x * S.x;
        float ey = p[j].y * S.y;
        float ez = p[j].z * S.z;
        float ew = p[j].w * S.w;
        uint2 o;
        __half2 ha = __floats2half2_rn(cn_out(ex, cw), cn_out(ey, cw));
        __half2 hb = __floats2half2_rn(cn_out(ez, cw), cn_out(ew, cw));
        o.x = *reinterpret_cast<unsigned*>(&ha);
        o.y = *reinterpret_cast<unsigned*>(&hb);
        wp[wof[j]] = o;
        S.x *= t[j].x;
        S.y *= t[j].y;
        S.z *= t[j].z;
        S.w *= t[j].w;
    }
}

// ---------------- final: dec = llr_in + sum c2v, transposed out ------------
__global__ void k_out(const float* __restrict__ in, float* __restrict__ out,
                      int fb) {
    __shared__ float tile[BSZ * 33];
    const __half* cv = reinterpret_cast<const __half*>(g_c2v + fb * BUFU2);
    int n0 = blockIdx.x * 32;
    int t = threadIdx.x;
#pragma unroll
    for (int k = 0; k < 8; k++) {       // b-fast mapping: coalesced plane reads
        int idx = t + k * 256;
        int b = idx & 63, nn = idx >> 6;
        int n = n0 + nn;
        float s = ((__half2float(cv[0 * N_VN * BSZ + n * BSZ + b]) +
                    __half2float(cv[1 * N_VN * BSZ + n * BSZ + b])) +
                    __half2float(cv[2 * N_VN * BSZ + n * BSZ + b])) +
                    __half2float(cv[3 * N_VN * BSZ + n * BSZ + b]);
        tile[b * 33 + nn] = s;
    }
    __syncthreads();
#pragma unroll
    for (int k = 0; k < 8; k++) {       // n-fast mapping: coalesced out writes
        int idx = t + k * 256;
        int nn = idx & 31, b = idx >> 5;
        out[b * N_VN + n0 + nn] = in[b * N_VN + n0 + nn] + tile[b * 33 + nn];
    }
}

// ---------------- launch ----------------
extern "C" void kernel_launch(void* const* d_in, const int* in_sizes, int n_in,
                              void* d_out, int out_size) {
    const float* llr  = (const float*)d_in[0];
    const float* cn_w = (const float*)d_in[1];
    const float* ch_w = (const float*)d_in[2];
    const int*   e2v  = (const int*)d_in[3];
    int iters = in_sizes[1];   // cn_weight length

    k_setup<<<N_VN / 32, 256>>>(llr);
    k_build_inverse<<<(E_EDGES + 255) / 256, 256>>>(e2v);
    k_sort4<<<(N_VN + 255) / 256, 256>>>();

    for (int it = 0; it < iters; it++)
        k_cn<<<(M_CN * 16) / 256, 256>>>(cn_w, ch_w, it, it & 1);

    k_out<<<N_VN / 32, 256>>>(llr, (float*)d_out, iters & 1);
}